// round 3
// baseline (speedup 1.0000x reference)
#include <cuda_runtime.h>
#include <math.h>

#define POINCARE_BOUND 0.99999f   // 1 - 1e-5
typedef unsigned long long u64;

// ---------------------------------------------------------------------------
// shared-memory layout (floats). Each matrix stored as two half-copies:
//   half h holds columns [h*OH, (h+1)*OH) contiguously, row stride OH.
//   Half copies separated by a stride whose bank offset (mod 32) = 8,
//   so the two per-warp LDS addresses never conflict.
// ---------------------------------------------------------------------------
constexpr int OFF_WC1 = 0;                 // 32x64, OH=32, half size 1024
constexpr int HS_WC1  = 1032;
constexpr int OFF_WC2 = OFF_WC1 + 2056;
constexpr int HS_WC2  = 1032;
constexpr int OFF_W0  = OFF_WC2 + 2056;    // 64x64, OH=32, half size 2048
constexpr int HS_W0   = 2056;
constexpr int OFF_W1  = OFF_W0 + 4104;     // 64x32, OH=16, half size 1024
constexpr int HS_W1   = 1032;
constexpr int OFF_BC  = OFF_W1 + 2056;     // 64,    OH=32
constexpr int HS_BC   = 40;
constexpr int OFF_B0  = OFF_BC + 72;
constexpr int HS_B0   = 40;
constexpr int OFF_B1  = OFF_B0 + 72;       // 32,    OH=16
constexpr int HS_B1   = 24;
constexpr int SMEM_FLOATS = OFF_B1 + 40;   // 10456 floats = 41.8 KB

// ---------------------------------------------------------------------------
// packed f32x2 helpers
// ---------------------------------------------------------------------------
__device__ __forceinline__ u64 pk2(float lo, float hi) {
    u64 r; asm("mov.b64 %0, {%1, %2};" : "=l"(r) : "f"(lo), "f"(hi)); return r;
}
__device__ __forceinline__ void upk2(u64 v, float& lo, float& hi) {
    asm("mov.b64 {%0, %1}, %2;" : "=f"(lo), "=f"(hi) : "l"(v));
}
__device__ __forceinline__ u64 fma2(u64 a, u64 b, u64 c) {
    u64 d; asm("fma.rn.f32x2 %0, %1, %2, %3;" : "=l"(d) : "l"(a), "l"(b), "l"(c)); return d;
}

__device__ __forceinline__ float pairsum(float p) {
    return p + __shfl_xor_sync(0xffffffffu, p, 16);
}

// ---------------------------------------------------------------------------
// half-row math helpers (D = dims owned by this thread; partner owns the rest)
// ---------------------------------------------------------------------------
template<int D>
__device__ __forceinline__ void logmap0_half(float* v) {
    float ss = 0.f;
#pragma unroll
    for (int i = 0; i < D; ++i) ss = fmaf(v[i], v[i], ss);
    ss = pairsum(ss);
    float n = fmaxf(sqrtf(ss), 1e-15f);
    float s = atanhf(fminf(n, POINCARE_BOUND)) / n;
#pragma unroll
    for (int i = 0; i < D; ++i) v[i] *= s;
}

template<int D>
__device__ __forceinline__ void expmap0_half(float* v) {
    float ss = 0.f;
#pragma unroll
    for (int i = 0; i < D; ++i) ss = fmaf(v[i], v[i], ss);
    ss = pairsum(ss);
    float n = fmaxf(sqrtf(ss), 1e-15f);
    float s = tanhf(n) / n;
#pragma unroll
    for (int i = 0; i < D; ++i) v[i] *= s;
}

// o = mobius_add(x, y) on this thread's half; y indexable (regs or smem)
template<int D, typename YT>
__device__ __forceinline__ void mobius_add_half(const float* x, YT y, float* o) {
    float x2 = 0.f, y2 = 0.f, xy = 0.f;
#pragma unroll
    for (int i = 0; i < D; ++i) {
        float yi = y[i];
        x2 = fmaf(x[i], x[i], x2);
        y2 = fmaf(yi, yi, y2);
        xy = fmaf(x[i], yi, xy);
    }
    x2 = pairsum(x2); y2 = pairsum(y2); xy = pairsum(xy);
    float a   = 1.f + 2.f * xy + y2;
    float b   = 1.f - x2;
    float den = fmaxf(1.f + 2.f * xy + x2 * y2, 1e-15f);
    float inv = 1.f / den;
#pragma unroll
    for (int i = 0; i < D; ++i) o[i] = (a * x[i] + b * y[i]) * inv;
}

// o[OH] = v[IN] @ Whalf[IN][OH]  (Whalf = this half's columns, in smem)
template<int IN, int OH>
__device__ __forceinline__ void matvec_half(const float* v, const float* sw, float* o) {
    u64 acc[OH / 2];
#pragma unroll
    for (int j = 0; j < OH / 2; ++j) acc[j] = 0ull;
#pragma unroll
    for (int k = 0; k < IN; ++k) {
        const u64 vv = pk2(v[k], v[k]);
        const u64* wr = reinterpret_cast<const u64*>(sw + k * OH);
#pragma unroll
        for (int j = 0; j < OH / 2; ++j) acc[j] = fma2(vv, wr[j], acc[j]);
    }
#pragma unroll
    for (int j = 0; j < OH / 2; ++j) upk2(acc[j], o[2 * j], o[2 * j + 1]);
}

// rebuild full 64-vector from the pair's two 32-halves
__device__ __forceinline__ void exchange32(const float* h, int half, float* full) {
#pragma unroll
    for (int i = 0; i < 32; ++i) {
        float oth = __shfl_xor_sync(0xffffffffu, h[i], 16);
        full[i]      = half ? oth  : h[i];
        full[i + 32] = half ? h[i] : oth;
    }
}

// load full 32-wide input row and apply logmap0 (no reduction needed: full row)
__device__ __forceinline__ void load_log32(const float* __restrict__ gx, int row, float* u) {
    const float4* xp = reinterpret_cast<const float4*>(gx + (size_t)row * 32);
    float ss = 0.f;
#pragma unroll
    for (int i = 0; i < 8; ++i) {
        float4 v = xp[i];
        u[4 * i + 0] = v.x; u[4 * i + 1] = v.y;
        u[4 * i + 2] = v.z; u[4 * i + 3] = v.w;
        ss = fmaf(v.x, v.x, ss); ss = fmaf(v.y, v.y, ss);
        ss = fmaf(v.z, v.z, ss); ss = fmaf(v.w, v.w, ss);
    }
    float n = fmaxf(sqrtf(ss), 1e-15f);
    float s = atanhf(fminf(n, POINCARE_BOUND)) / n;
#pragma unroll
    for (int i = 0; i < 32; ++i) u[i] *= s;
}

// ---------------------------------------------------------------------------
// cooperative smem fill with per-half reordering
// ---------------------------------------------------------------------------
__device__ __forceinline__ void fill_mat(float* s, const float* g, int IN, int OUT,
                                         int off, int hs, int tid, int nthr) {
    const int OH = OUT / 2;
    for (int idx = tid; idx < IN * OUT; idx += nthr) {
        int k = idx / OUT, j0 = idx % OUT;
        int half = j0 / OH, j = j0 % OH;
        s[off + half * hs + k * OH + j] = g[idx];
    }
}
__device__ __forceinline__ void fill_vec(float* s, const float* g, int OUT,
                                         int off, int hs, int tid, int nthr) {
    const int OH = OUT / 2;
    for (int i = tid; i < OUT; i += nthr) {
        int half = i / OH;
        s[off + half * hs + (i % OH)] = g[i];
    }
}

// ---------------------------------------------------------------------------
// kernel: two threads (lanes L, L^16) per row; weights in padded smem halves
// ---------------------------------------------------------------------------
__global__ void __launch_bounds__(128, 4)
poincare_mlp_kernel(const float* __restrict__ gx1,
                    const float* __restrict__ gx2,
                    const float* __restrict__ gWc1,
                    const float* __restrict__ gWc2,
                    const float* __restrict__ gbc,
                    const float* __restrict__ gW0,
                    const float* __restrict__ gb0,
                    const float* __restrict__ gW1,
                    const float* __restrict__ gb1,
                    float* __restrict__ gout,
                    int N)
{
    __shared__ __align__(16) float s[SMEM_FLOATS];
    const int tid = threadIdx.x;
    fill_mat(s, gWc1, 32, 64, OFF_WC1, HS_WC1, tid, 128);
    fill_mat(s, gWc2, 32, 64, OFF_WC2, HS_WC2, tid, 128);
    fill_mat(s, gW0,  64, 64, OFF_W0,  HS_W0,  tid, 128);
    fill_mat(s, gW1,  64, 32, OFF_W1,  HS_W1,  tid, 128);
    fill_vec(s, gbc, 64, OFF_BC, HS_BC, tid, 128);
    fill_vec(s, gb0, 64, OFF_B0, HS_B0, tid, 128);
    fill_vec(s, gb1, 32, OFF_B1, HS_B1, tid, 128);
    __syncthreads();

    const int lane = tid & 31;
    const int half = lane >> 4;          // 0: dims [0,32), 1: dims [32,64)
    const int rw   = lane & 15;          // row within warp
    const int gw   = blockIdx.x * 4 + (tid >> 5);
    int row = gw * 16 + rw;
    row = row < N ? row : N - 1;         // clamp: duplicate lanes write identical data

    const float* sWc1h = s + OFF_WC1 + half * HS_WC1;
    const float* sWc2h = s + OFF_WC2 + half * HS_WC2;
    const float* sW0h  = s + OFF_W0  + half * HS_W0;
    const float* sW1h  = s + OFF_W1  + half * HS_W1;
    const float* sbch  = s + OFF_BC  + half * HS_BC;
    const float* sb0h  = s + OFF_B0  + half * HS_B0;
    const float* sb1h  = s + OFF_B1  + half * HS_B1;

    float u[32];
    float h1[32];
    float h2[32];

    // ---- branch 1: h1 = expmap0(logmap0(x1) @ Wc1)  (this half's 32 outputs)
    load_log32(gx1, row, u);
    matvec_half<32, 32>(u, sWc1h, h1);
    expmap0_half<32>(h1);

    // ---- branch 2
    load_log32(gx2, row, u);
    matvec_half<32, 32>(u, sWc2h, h2);
    expmap0_half<32>(h2);

    // ---- h = mobius_add(mobius_add(h1, h2), bc)
    float h[32];
    mobius_add_half<32>(h1, h2, h);
    mobius_add_half<32>(h, sbch, h1);    // h1 <- concat output (half)

    // ---- layer 0: mobius_add(expmap0(logmap0(h) @ W0), b0)
    logmap0_half<32>(h1);
    {
        float full[64];
        exchange32(h1, half, full);
        matvec_half<64, 32>(full, sW0h, h2);
    }
    expmap0_half<32>(h2);
    mobius_add_half<32>(h2, sb0h, h1);   // h1 <- layer0 output (half)

    // ---- layer 1: mobius_add(expmap0(logmap0(h) @ W1), b1)
    logmap0_half<32>(h1);
    float o[16];
    {
        float full[64];
        exchange32(h1, half, full);
        matvec_half<64, 16>(full, sW1h, o);
    }
    expmap0_half<16>(o);
    float ov[16];
    mobius_add_half<16>(o, sb1h, ov);

    float4* op = reinterpret_cast<float4*>(gout + (size_t)row * 32 + half * 16);
#pragma unroll
    for (int i = 0; i < 4; ++i)
        op[i] = make_float4(ov[4 * i + 0], ov[4 * i + 1], ov[4 * i + 2], ov[4 * i + 3]);
}

// ---------------------------------------------------------------------------
// launch
// ---------------------------------------------------------------------------
extern "C" void kernel_launch(void* const* d_in, const int* in_sizes, int n_in,
                              void* d_out, int out_size)
{
    const float* x1  = (const float*)d_in[0];
    const float* x2  = (const float*)d_in[1];
    const float* Wc1 = (const float*)d_in[2];
    const float* Wc2 = (const float*)d_in[3];
    const float* bc  = (const float*)d_in[4];
    const float* W0  = (const float*)d_in[5];
    const float* b0  = (const float*)d_in[6];
    const float* W1  = (const float*)d_in[7];
    const float* b1  = (const float*)d_in[8];
    float* out = (float*)d_out;

    const int N = in_sizes[0] / 32;
    const int rows_per_block = 64;                    // 4 warps x 16 rows
    const int blocks = (N + rows_per_block - 1) / rows_per_block;
    poincare_mlp_kernel<<<blocks, 128>>>(x1, x2, Wc1, Wc2, bc, W0, b0, W1, b1, out, N);
}

// round 4
// speedup vs baseline: 1.3519x; 1.3519x over previous
#include <cuda_runtime.h>
#include <math.h>

#define POINCARE_BOUND 0.99999f   // 1 - 1e-5
typedef unsigned long long u64;

// ---------------------------------------------------------------------------
// constant-memory weights (uniform addresses -> LDCU uniform-const port)
// ---------------------------------------------------------------------------
__constant__ __align__(16) float cWc1[32 * 64];
__constant__ __align__(16) float cWc2[32 * 64];
__constant__ __align__(16) float cW0 [64 * 64];
__constant__ __align__(16) float cW1 [64 * 32];
__constant__ __align__(16) float cbc [64];
__constant__ __align__(16) float cb0 [64];
__constant__ __align__(16) float cb1 [32];

// ---------------------------------------------------------------------------
// packed f32x2 primitives
// ---------------------------------------------------------------------------
__device__ __forceinline__ u64 pk2(float lo, float hi) {
    u64 r; asm("mov.b64 %0, {%1, %2};" : "=l"(r) : "f"(lo), "f"(hi)); return r;
}
__device__ __forceinline__ void upk2(u64 v, float& lo, float& hi) {
    asm("mov.b64 {%0, %1}, %2;" : "=f"(lo), "=f"(hi) : "l"(v));
}
__device__ __forceinline__ u64 fma2(u64 a, u64 b, u64 c) {
    u64 d; asm("fma.rn.f32x2 %0, %1, %2, %3;" : "=l"(d) : "l"(a), "l"(b), "l"(c)); return d;
}
__device__ __forceinline__ u64 mul2(u64 a, u64 b) {
    u64 d; asm("mul.rn.f32x2 %0, %1, %2;" : "=l"(d) : "l"(a), "l"(b)); return d;
}
__device__ __forceinline__ float hsum2(u64 v) {
    float lo, hi; upk2(v, lo, hi); return lo + hi;
}

// ---------------------------------------------------------------------------
// fast scalar math (MUFU approx paths; all norms here are O(1), safe)
// ---------------------------------------------------------------------------
__device__ __forceinline__ float rcpf(float x)  { float r; asm("rcp.approx.f32 %0, %1;"  : "=f"(r) : "f"(x)); return r; }
__device__ __forceinline__ float sqrtfa(float x){ float r; asm("sqrt.approx.f32 %0, %1;" : "=f"(r) : "f"(x)); return r; }
__device__ __forceinline__ float lg2fa(float x) { float r; asm("lg2.approx.f32 %0, %1;"  : "=f"(r) : "f"(x)); return r; }
__device__ __forceinline__ float ex2fa(float x) { float r; asm("ex2.approx.f32 %0, %1;"  : "=f"(r) : "f"(x)); return r; }

// atanh(min(n,B))/n  with n = sqrt(ss)
__device__ __forceinline__ float log_scale(float ss) {
    float n  = fmaxf(sqrtfa(ss), 1e-15f);
    float m  = fminf(n, POINCARE_BOUND);
    float r  = (1.f + m) * rcpf(1.f - m);
    float at = 0.34657359f * lg2fa(r);          // 0.5*ln(2)*log2(r)
    return at * rcpf(n);
}
// tanh(n)/n  with n = sqrt(ss)
__device__ __forceinline__ float exp_scale(float ss) {
    float n = fmaxf(sqrtfa(ss), 1e-15f);
    float e = ex2fa(n * -2.8853901f);           // exp(-2n)
    float t = (1.f - e) * rcpf(1.f + e);
    return t * rcpf(n);
}

// ---------------------------------------------------------------------------
// packed vector ops (D2 = number of u64 = dims/2)
// ---------------------------------------------------------------------------
template<int D2>
__device__ __forceinline__ float ssum2(const u64* v) {
    u64 a = 0ull;
#pragma unroll
    for (int i = 0; i < D2; ++i) a = fma2(v[i], v[i], a);
    return hsum2(a);
}
template<int D2>
__device__ __forceinline__ void scale2(u64* v, float s) {
    const u64 s2 = pk2(s, s);
#pragma unroll
    for (int i = 0; i < D2; ++i) v[i] = mul2(v[i], s2);
}
template<int D2>
__device__ __forceinline__ void logmap0p(u64* v) { scale2<D2>(v, log_scale(ssum2<D2>(v))); }
template<int D2>
__device__ __forceinline__ void expmap0p(u64* v) { scale2<D2>(v, exp_scale(ssum2<D2>(v))); }

// o = mobius_add(x, y); all packed. y may be constant memory.
template<int D2>
__device__ __forceinline__ void mobius_addp(const u64* x, const u64* y, u64* o) {
    u64 ax = 0ull, ay = 0ull, axy = 0ull;
#pragma unroll
    for (int i = 0; i < D2; ++i) {
        u64 yi = y[i];
        ax  = fma2(x[i], x[i], ax);
        ay  = fma2(yi,  yi,  ay);
        axy = fma2(x[i], yi, axy);
    }
    float x2 = hsum2(ax), y2 = hsum2(ay), xy = hsum2(axy);
    float a   = 1.f + 2.f * xy + y2;
    float b   = 1.f - x2;
    float inv = rcpf(fmaxf(1.f + 2.f * xy + x2 * y2, 1e-15f));
    const u64 a2 = pk2(a * inv, a * inv);
    const u64 b2 = pk2(b * inv, b * inv);
#pragma unroll
    for (int i = 0; i < D2; ++i)
        o[i] = fma2(b2, y[i], mul2(a2, x[i]));
}

// o2[OUT/2] = v2[IN/2] @ W[IN][OUT], W in __constant__, chunked outputs
template<int IN, int OUT, int CH>
__device__ __forceinline__ void matvecC2(const u64* v2, const float* cW, u64* o2) {
#pragma unroll
    for (int c0 = 0; c0 < OUT; c0 += CH) {
        u64 acc[CH / 2];
#pragma unroll
        for (int j = 0; j < CH / 2; ++j) acc[j] = 0ull;
#pragma unroll
        for (int k2 = 0; k2 < IN / 2; ++k2) {
            float lo, hi; upk2(v2[k2], lo, hi);
            const u64 va = pk2(lo, lo), vb = pk2(hi, hi);
            const u64* w0 = reinterpret_cast<const u64*>(cW + (2 * k2)     * OUT + c0);
            const u64* w1 = reinterpret_cast<const u64*>(cW + (2 * k2 + 1) * OUT + c0);
#pragma unroll
            for (int j = 0; j < CH / 2; ++j) {
                acc[j] = fma2(va, w0[j], acc[j]);
                acc[j] = fma2(vb, w1[j], acc[j]);
            }
        }
#pragma unroll
        for (int j = 0; j < CH / 2; ++j) o2[c0 / 2 + j] = acc[j];
    }
}

// load one 32-wide row, pack, apply logmap0
__device__ __forceinline__ void load_log32p(const float* __restrict__ gx, int row, u64* v2) {
    const float4* xp = reinterpret_cast<const float4*>(gx + (size_t)row * 32);
    u64 a = 0ull;
#pragma unroll
    for (int i = 0; i < 8; ++i) {
        float4 v = xp[i];
        u64 p0 = pk2(v.x, v.y), p1 = pk2(v.z, v.w);
        v2[2 * i] = p0; v2[2 * i + 1] = p1;
        a = fma2(p0, p0, a);
        a = fma2(p1, p1, a);
    }
    scale2<16>(v2, log_scale(hsum2(a)));
}

// ---------------------------------------------------------------------------
// kernel: one thread per row; constant weights; packed f32x2 everywhere
// ---------------------------------------------------------------------------
__global__ void __launch_bounds__(128, 4)
poincare_mlp_kernel(const float* __restrict__ gx1,
                    const float* __restrict__ gx2,
                    float* __restrict__ gout,
                    int N)
{
    const int row = blockIdx.x * 128 + threadIdx.x;
    if (row >= N) return;

    u64 u2[16];
    u64 h1[32], h2[32], hh[32];

    // ---- branch 1: h1 = expmap0(logmap0(x1) @ Wc1)
    load_log32p(gx1, row, u2);
    matvecC2<32, 64, 32>(u2, cWc1, h1);
    expmap0p<32>(h1);

    // ---- branch 2: h2 = expmap0(logmap0(x2) @ Wc2)
    load_log32p(gx2, row, u2);
    matvecC2<32, 64, 32>(u2, cWc2, h2);
    expmap0p<32>(h2);

    // ---- h = mobius_add(mobius_add(h1, h2), bc)
    mobius_addp<32>(h1, h2, hh);
    mobius_addp<32>(hh, reinterpret_cast<const u64*>(cbc), h1);   // h1 <- concat out

    // ---- layer 0: mobius_add(expmap0(logmap0(h) @ W0), b0)
    logmap0p<32>(h1);
    matvecC2<64, 64, 32>(h1, cW0, h2);
    expmap0p<32>(h2);
    mobius_addp<32>(h2, reinterpret_cast<const u64*>(cb0), hh);   // hh <- layer0 out

    // ---- layer 1: mobius_add(expmap0(logmap0(h) @ W1), b1)
    logmap0p<32>(hh);
    u64 o2[16];
    matvecC2<64, 32, 32>(hh, cW1, o2);
    expmap0p<16>(o2);
    u64 ov[16];
    mobius_addp<16>(o2, reinterpret_cast<const u64*>(cb1), ov);

    float4* op = reinterpret_cast<float4*>(gout + (size_t)row * 32);
#pragma unroll
    for (int i = 0; i < 8; ++i) {
        float x, y, z, w;
        upk2(ov[2 * i],     x, y);
        upk2(ov[2 * i + 1], z, w);
        op[i] = make_float4(x, y, z, w);
    }
}

// ---------------------------------------------------------------------------
// launch
// ---------------------------------------------------------------------------
extern "C" void kernel_launch(void* const* d_in, const int* in_sizes, int n_in,
                              void* d_out, int out_size)
{
    const float* x1 = (const float*)d_in[0];
    const float* x2 = (const float*)d_in[1];

    cudaMemcpyToSymbolAsync(cWc1, d_in[2], 32 * 64 * sizeof(float), 0, cudaMemcpyDeviceToDevice);
    cudaMemcpyToSymbolAsync(cWc2, d_in[3], 32 * 64 * sizeof(float), 0, cudaMemcpyDeviceToDevice);
    cudaMemcpyToSymbolAsync(cbc,  d_in[4], 64 * sizeof(float),      0, cudaMemcpyDeviceToDevice);
    cudaMemcpyToSymbolAsync(cW0,  d_in[5], 64 * 64 * sizeof(float), 0, cudaMemcpyDeviceToDevice);
    cudaMemcpyToSymbolAsync(cb0,  d_in[6], 64 * sizeof(float),      0, cudaMemcpyDeviceToDevice);
    cudaMemcpyToSymbolAsync(cW1,  d_in[7], 64 * 32 * sizeof(float), 0, cudaMemcpyDeviceToDevice);
    cudaMemcpyToSymbolAsync(cb1,  d_in[8], 32 * sizeof(float),      0, cudaMemcpyDeviceToDevice);

    float* out = (float*)d_out;
    const int N = in_sizes[0] / 32;
    const int blocks = (N + 127) / 128;
    poincare_mlp_kernel<<<blocks, 128>>>(x1, x2, out, N);
}